// round 6
// baseline (speedup 1.0000x reference)
#include <cuda_runtime.h>
#include <cuda_fp16.h>
#include <math.h>

#define NN 100000
#define EE 1600000
#define ET (EE + NN)
#define FEAT 128
#define HC 64
#define NH 4
#define NC 40
#define SLOPE 0.2f
#define BNEPS 1e-5f
#define NB ((NN + 1023) / 1024)

typedef unsigned long long ull;

// ---------------- scratch ----------------
__device__ __half g_h1[NN * HC];    // layer-1 features, fp16 (gathered in agg1)
__device__ float  g_o1[NN * HC];    // layer-1 GAT output, fp32 (feeds gemm2)
__device__ __half g_h2[NN * NC];    // layer-2 features, fp16 (gathered in agg2)
__device__ float  g_as1[NN * NH];
__device__ float  g_ad1[NN * NH];
__device__ float  g_as2[NN];
__device__ float  g_ad2[NN];
__device__ int    g_rowptr[NN + 1];
__device__ int    g_cursor[NN];
__device__ int    g_cnt[NN];        // zero-initialized; every launch restores to zero
__device__ int    g_srcs[ET];
__device__ int    g_bsum[128];

// ---------------- f32x2 helpers ----------------
__device__ __forceinline__ ull fma2(ull a, ull b, ull c) {
    ull d;
    asm("fma.rn.f32x2 %0, %1, %2, %3;" : "=l"(d) : "l"(a), "l"(b), "l"(c));
    return d;
}
__device__ __forceinline__ ull splat2(float x) {
    ull r;
    asm("mov.b64 %0, {%1, %1};" : "=l"(r) : "f"(x));
    return r;
}
__device__ __forceinline__ void unpack2(ull v, float& lo, float& hi) {
    asm("mov.b64 {%0, %1}, %2;" : "=f"(lo), "=f"(hi) : "l"(v));
}

union HalfPack {
    __half2 h[2];
    uint2 u;
};

__device__ __forceinline__ int probe_is64(const void* ei) {
    const long long* p = (const long long*)ei;
    int is64 = 1;
#pragma unroll
    for (int j = 0; j < 8; j++) {
        long long v = p[j];
        if (v < 0 || v >= NN) { is64 = 0; break; }
    }
    return is64;
}

// ---------------- histogram (reads edge_index directly) ----------------
__global__ void k_hist(const void* ei) {
    __shared__ int sh_is64;
    if (threadIdx.x == 0) sh_is64 = probe_is64(ei);
    __syncthreads();
    int e = blockIdx.x * blockDim.x + threadIdx.x;
    if (e >= ET) return;
    int dst;
    if (e < EE) {
        dst = sh_is64 ? (int)((const long long*)ei)[EE + e] : ((const int*)ei)[EE + e];
    } else {
        dst = e - EE;
    }
    atomicAdd(&g_cnt[dst], 1);   // no return use -> RED
}

// ---------------- scan: per-block scan (restores g_cnt to zero), then fused fixup ----------------
__global__ void k_scan1() {  // blockDim = 1024
    int i = blockIdx.x * 1024 + threadIdx.x;
    int v = 0;
    if (i < NN) {
        v = g_cnt[i];
        g_cnt[i] = 0;           // restore invariant for next launch
    }
    int x = v;
#pragma unroll
    for (int o = 1; o < 32; o <<= 1) {
        int y = __shfl_up_sync(0xffffffffu, x, o);
        if ((threadIdx.x & 31) >= o) x += y;
    }
    __shared__ int ws[32];
    if ((threadIdx.x & 31) == 31) ws[threadIdx.x >> 5] = x;
    __syncthreads();
    if (threadIdx.x < 32) {
        int w = ws[threadIdx.x];
#pragma unroll
        for (int o = 1; o < 32; o <<= 1) {
            int y = __shfl_up_sync(0xffffffffu, w, o);
            if (threadIdx.x >= o) w += y;
        }
        ws[threadIdx.x] = w;
    }
    __syncthreads();
    int add = (threadIdx.x >= 32) ? ws[(threadIdx.x >> 5) - 1] : 0;
    int incl = x + add;
    if (i < NN) g_rowptr[i] = incl - v;
    if (threadIdx.x == 1023) g_bsum[blockIdx.x] = incl;
}

__global__ void k_scan3() {
    __shared__ int sb[128];
    int tid = threadIdx.x;
    if (tid < 128) sb[tid] = (tid < NB) ? g_bsum[tid] : 0;
    __syncthreads();
#pragma unroll
    for (int o = 1; o < 128; o <<= 1) {
        int t = 0;
        if (tid < 128 && tid >= o) t = sb[tid - o];
        __syncthreads();
        if (tid < 128) sb[tid] += t;
        __syncthreads();
    }
    int i = blockIdx.x * blockDim.x + tid;
    if (i < NN) {
        int blk = i >> 10;
        int r = g_rowptr[i] + (blk ? sb[blk - 1] : 0);
        g_rowptr[i] = r;
        g_cursor[i] = r;
    }
    if (i == 0) g_rowptr[NN] = ET;
}

// ---------------- scatter: 4 edges/thread for atomic MLP; reads ei directly ----------------
__global__ void k_scatter(const void* ei) {
    __shared__ int sh_is64;
    if (threadIdx.x == 0) sh_is64 = probe_is64(ei);
    __syncthreads();
    int base = (blockIdx.x * blockDim.x + threadIdx.x) * 4;
    if (base >= ET) return;
    int is64 = sh_is64;

    int src[4], dst[4];
#pragma unroll
    for (int j = 0; j < 4; j++) {
        int e = base + j;
        if (e < ET) {
            if (e < EE) {
                if (is64) {
                    src[j] = (int)((const long long*)ei)[e];
                    dst[j] = (int)((const long long*)ei)[EE + e];
                } else {
                    src[j] = ((const int*)ei)[e];
                    dst[j] = ((const int*)ei)[EE + e];
                }
            } else {
                src[j] = e - EE;
                dst[j] = src[j];
            }
        }
    }
    int pos[4];
#pragma unroll
    for (int j = 0; j < 4; j++)
        if (base + j < ET) pos[j] = atomicAdd(&g_cursor[dst[j]], 1);
#pragma unroll
    for (int j = 0; j < 4; j++)
        if (base + j < ET) g_srcs[pos[j]] = src[j];
}

// ---------------- GEMM1: h1 = x @ W1, fused attention scalars (f32x2), fp16 h1 store ----------------
__global__ void k_gemm1(const float* __restrict__ x, const float* __restrict__ W,
                        const float* __restrict__ attS, const float* __restrict__ attD) {
    __shared__ __align__(16) float As[32][130];
    __shared__ __align__(16) float Bs[32][64];
    int tid = threadIdx.x;
    int tx = tid & 15, ty = tid >> 4;
    int mBase = blockIdx.x * 128;

    float as_v[4], ad_v[4];
#pragma unroll
    for (int j = 0; j < 4; j++) {
        as_v[j] = attS[tx * 4 + j];
        ad_v[j] = attD[tx * 4 + j];
    }

    ull acc[4][4];
#pragma unroll
    for (int p = 0; p < 4; p++)
#pragma unroll
        for (int j = 0; j < 4; j++) acc[p][j] = 0ull;

    for (int k0 = 0; k0 < FEAT; k0 += 32) {
        for (int idx = tid; idx < 128 * 32; idx += 256) {
            int m = idx >> 5, kk = idx & 31;
            int gm = mBase + m;
            As[kk][m] = (gm < NN) ? x[gm * FEAT + k0 + kk] : 0.f;
        }
        for (int idx = tid; idx < 32 * 64; idx += 256)
            Bs[idx >> 6][idx & 63] = W[(k0 + (idx >> 6)) * HC + (idx & 63)];
        __syncthreads();
#pragma unroll
        for (int kk = 0; kk < 32; kk++) {
            float4 bv = *(const float4*)&Bs[kk][tx * 4];
            ull b0 = splat2(bv.x), b1 = splat2(bv.y), b2 = splat2(bv.z), b3 = splat2(bv.w);
#pragma unroll
            for (int p = 0; p < 4; p++) {
                ull a = *(const ull*)&As[kk][ty * 8 + 2 * p];
                acc[p][0] = fma2(a, b0, acc[p][0]);
                acc[p][1] = fma2(a, b1, acc[p][1]);
                acc[p][2] = fma2(a, b2, acc[p][2]);
                acc[p][3] = fma2(a, b3, acc[p][3]);
            }
        }
        __syncthreads();
    }

#pragma unroll
    for (int p = 0; p < 4; p++) {
        float lo[4], hi[4];
#pragma unroll
        for (int j = 0; j < 4; j++) unpack2(acc[p][j], lo[j], hi[j]);
#pragma unroll
        for (int half = 0; half < 2; half++) {
            float* f = half ? hi : lo;
            int r = 2 * p + half;
            int gm = mBase + ty * 8 + r;
            if (gm < NN) {
                HalfPack hp;
                hp.h[0] = __floats2half2_rn(f[0], f[1]);
                hp.h[1] = __floats2half2_rn(f[2], f[3]);
                *(uint2*)&g_h1[gm * HC + tx * 4] = hp.u;
                float ps = f[0] * as_v[0] + f[1] * as_v[1] + f[2] * as_v[2] + f[3] * as_v[3];
                float pd = f[0] * ad_v[0] + f[1] * ad_v[1] + f[2] * ad_v[2] + f[3] * ad_v[3];
                ps += __shfl_xor_sync(0xffffffffu, ps, 1);
                pd += __shfl_xor_sync(0xffffffffu, pd, 1);
                ps += __shfl_xor_sync(0xffffffffu, ps, 2);
                pd += __shfl_xor_sync(0xffffffffu, pd, 2);
                if ((tx & 3) == 0) {
                    g_as1[gm * NH + (tx >> 2)] = ps;
                    g_ad1[gm * NH + (tx >> 2)] = pd;
                }
            } else {
                float z = 0.f;
                z += __shfl_xor_sync(0xffffffffu, z, 1);
                z += __shfl_xor_sync(0xffffffffu, z, 1);
                z += __shfl_xor_sync(0xffffffffu, z, 2);
                z += __shfl_xor_sync(0xffffffffu, z, 2);
            }
        }
    }
}

// ---------------- layer-1 aggregation: fused pass, fp16 gathers ----------------
__global__ void k_agg1(const float* __restrict__ bias) {
    int t = blockIdx.x * blockDim.x + threadIdx.x;
    int node = t >> 5, lane = t & 31;
    if (node >= NN) return;
    int beg = g_rowptr[node], end = g_rowptr[node + 1];
    float4 adv = *(const float4*)&g_ad1[node * NH];

    int half = lane >> 4;        // which edge of the pair
    int l = lane & 15;           // channel group: channels l*4 .. l*4+3
    int hsel = l >> 2;           // head
    float adh = (hsel == 0) ? adv.x : (hsel == 1) ? adv.y : (hsel == 2) ? adv.z : adv.w;

    float4 acc = make_float4(0.f, 0.f, 0.f, 0.f);
    float sex = 0.f;
    int i = beg + half;
    int s = (i < end) ? g_srcs[i] : 0;
    while (i < end) {
        int inext = i + 2;
        int snext = (inext < end) ? g_srcs[inext] : 0;
        float a = g_as1[s * NH + hsel] + adh;
        a = fmaxf(a, SLOPE * a);
        float ex = __expf(a);
        HalfPack hp;
        hp.u = *(const uint2*)&g_h1[s * HC + l * 4];
        float2 f01 = __half22float2(hp.h[0]);
        float2 f23 = __half22float2(hp.h[1]);
        acc.x += ex * f01.x; acc.y += ex * f01.y;
        acc.z += ex * f23.x; acc.w += ex * f23.y;
        sex += ex;
        i = inext; s = snext;
    }
    acc.x += __shfl_xor_sync(0xffffffffu, acc.x, 16);
    acc.y += __shfl_xor_sync(0xffffffffu, acc.y, 16);
    acc.z += __shfl_xor_sync(0xffffffffu, acc.z, 16);
    acc.w += __shfl_xor_sync(0xffffffffu, acc.w, 16);
    sex   += __shfl_xor_sync(0xffffffffu, sex, 16);

    if (half == 0) {
        float inv = 1.0f / sex;
        float4 bv = *(const float4*)&bias[l * 4];
        float4 o;
        o.x = acc.x * inv + bv.x;
        o.y = acc.y * inv + bv.y;
        o.z = acc.z * inv + bv.z;
        o.w = acc.w * inv + bv.w;
        *(float4*)&g_o1[node * HC + l * 4] = o;
    }
}

// ---------------- GEMM2: h2 = relu(BN(o1)) @ W2, fused attn scalars, fp16 h2 store ----------------
__global__ void k_gemm2(const float* __restrict__ W2,
                        const float* __restrict__ gamma, const float* __restrict__ beta,
                        const float* __restrict__ mean, const float* __restrict__ var,
                        const float* __restrict__ attS, const float* __restrict__ attD) {
    __shared__ __align__(16) float As[32][130];
    __shared__ __align__(16) float Bs[32][64];
    __shared__ float sc[64], sh[64];
    int tid = threadIdx.x;
    if (tid < 64) {
        float s = gamma[tid] * rsqrtf(var[tid] + BNEPS);
        sc[tid] = s;
        sh[tid] = beta[tid] - mean[tid] * s;
    }
    __syncthreads();
    int tx = tid & 15, ty = tid >> 4;
    int mBase = blockIdx.x * 128;

    float as_v[4], ad_v[4];
#pragma unroll
    for (int j = 0; j < 4; j++) {
        int c = tx * 4 + j;
        int cc = (c < NC) ? c : NC - 1;
        as_v[j] = attS[cc];
        ad_v[j] = attD[cc];
    }

    ull acc[4][4];
#pragma unroll
    for (int p = 0; p < 4; p++)
#pragma unroll
        for (int j = 0; j < 4; j++) acc[p][j] = 0ull;

    for (int k0 = 0; k0 < HC; k0 += 32) {
        for (int idx = tid; idx < 128 * 32; idx += 256) {
            int m = idx >> 5, kk = idx & 31;
            int gm = mBase + m;
            int k = k0 + kk;
            float v = (gm < NN) ? g_o1[gm * HC + k] : 0.f;
            As[kk][m] = fmaxf(v * sc[k] + sh[k], 0.f);
        }
        for (int idx = tid; idx < 32 * 64; idx += 256) {
            int r = idx >> 6, c = idx & 63;
            Bs[r][c] = (c < NC) ? W2[(k0 + r) * NC + c] : 0.f;
        }
        __syncthreads();
#pragma unroll
        for (int kk = 0; kk < 32; kk++) {
            float4 bv = *(const float4*)&Bs[kk][tx * 4];
            ull b0 = splat2(bv.x), b1 = splat2(bv.y), b2 = splat2(bv.z), b3 = splat2(bv.w);
#pragma unroll
            for (int p = 0; p < 4; p++) {
                ull a = *(const ull*)&As[kk][ty * 8 + 2 * p];
                acc[p][0] = fma2(a, b0, acc[p][0]);
                acc[p][1] = fma2(a, b1, acc[p][1]);
                acc[p][2] = fma2(a, b2, acc[p][2]);
                acc[p][3] = fma2(a, b3, acc[p][3]);
            }
        }
        __syncthreads();
    }

#pragma unroll
    for (int p = 0; p < 4; p++) {
        float lo[4], hi[4];
#pragma unroll
        for (int j = 0; j < 4; j++) unpack2(acc[p][j], lo[j], hi[j]);
#pragma unroll
        for (int half = 0; half < 2; half++) {
            float* f = half ? hi : lo;
            int r = 2 * p + half;
            int gm = mBase + ty * 8 + r;
            float ps = 0.f, pd = 0.f;
            if (gm < NN) {
                if (tx < 10) {
                    HalfPack hp;
                    hp.h[0] = __floats2half2_rn(f[0], f[1]);
                    hp.h[1] = __floats2half2_rn(f[2], f[3]);
                    *(uint2*)&g_h2[gm * NC + tx * 4] = hp.u;
                }
                ps = f[0] * as_v[0] + f[1] * as_v[1] + f[2] * as_v[2] + f[3] * as_v[3];
                pd = f[0] * ad_v[0] + f[1] * ad_v[1] + f[2] * ad_v[2] + f[3] * ad_v[3];
            }
#pragma unroll
            for (int o = 8; o >= 1; o >>= 1) {
                ps += __shfl_xor_sync(0xffffffffu, ps, o);
                pd += __shfl_xor_sync(0xffffffffu, pd, o);
            }
            if (gm < NN && tx == 0) {
                g_as2[gm] = ps;
                g_ad2[gm] = pd;
            }
        }
    }
}

// ---------------- layer-2 aggregation: fused pass, fp16 gathers ----------------
__global__ void k_agg2(const float* __restrict__ bias, float* __restrict__ out) {
    int t = blockIdx.x * blockDim.x + threadIdx.x;
    int node = t >> 5, lane = t & 31;
    if (node >= NN) return;
    int beg = g_rowptr[node], end = g_rowptr[node + 1];
    float ad = g_ad2[node];

    int grp = lane / 10;               // 0,1,2 active; lanes 30,31 idle
    int l = lane - grp * 10;           // 0..9
    float4 acc = make_float4(0.f, 0.f, 0.f, 0.f);
    float sex = 0.f;
    if (grp < 3) {
        int i = beg + grp;
        int s = (i < end) ? g_srcs[i] : 0;
        while (i < end) {
            int inext = i + 3;
            int snext = (inext < end) ? g_srcs[inext] : 0;
            float a = g_as2[s] + ad;
            a = fmaxf(a, SLOPE * a);
            float ex = __expf(a);
            HalfPack hp;
            hp.u = *(const uint2*)&g_h2[s * NC + l * 4];
            float2 f01 = __half22float2(hp.h[0]);
            float2 f23 = __half22float2(hp.h[1]);
            acc.x += ex * f01.x; acc.y += ex * f01.y;
            acc.z += ex * f23.x; acc.w += ex * f23.y;
            sex += ex;
            i = inext; s = snext;
        }
    }
    int s1 = l + 10, s2 = l + 20;
    acc.x += __shfl_sync(0xffffffffu, acc.x, s1) + __shfl_sync(0xffffffffu, acc.x, s2);
    acc.y += __shfl_sync(0xffffffffu, acc.y, s1) + __shfl_sync(0xffffffffu, acc.y, s2);
    acc.z += __shfl_sync(0xffffffffu, acc.z, s1) + __shfl_sync(0xffffffffu, acc.z, s2);
    acc.w += __shfl_sync(0xffffffffu, acc.w, s1) + __shfl_sync(0xffffffffu, acc.w, s2);
    sex   += __shfl_sync(0xffffffffu, sex, s1) + __shfl_sync(0xffffffffu, sex, s2);

    if (grp == 0) {
        float inv = 1.0f / sex;
        float4 bv = *(const float4*)&bias[l * 4];
        float4 o;
        o.x = acc.x * inv + bv.x;
        o.y = acc.y * inv + bv.y;
        o.z = acc.z * inv + bv.z;
        o.w = acc.w * inv + bv.w;
        *(float4*)&out[node * NC + l * 4] = o;
    }
}

// ---------------- launch (fork-join: CSR build overlaps GEMM1) ----------------
extern "C" void kernel_launch(void* const* d_in, const int* in_sizes, int n_in,
                              void* d_out, int out_size) {
    const float* x    = (const float*)d_in[0];
    const void*  ei   = d_in[1];
    const float* W1   = (const float*)d_in[2];
    const float* as1  = (const float*)d_in[3];
    const float* ad1  = (const float*)d_in[4];
    const float* b1   = (const float*)d_in[5];
    const float* bngm = (const float*)d_in[6];
    const float* bnbt = (const float*)d_in[7];
    const float* bnmu = (const float*)d_in[8];
    const float* bnvr = (const float*)d_in[9];
    const float* W2   = (const float*)d_in[10];
    const float* as2  = (const float*)d_in[11];
    const float* ad2  = (const float*)d_in[12];
    const float* b2   = (const float*)d_in[13];
    float*       out  = (float*)d_out;

    static cudaStream_t s2 = nullptr;
    static cudaEvent_t evA = nullptr, evB = nullptr;
    if (s2 == nullptr) {
        cudaStreamCreateWithFlags(&s2, cudaStreamNonBlocking);
        cudaEventCreateWithFlags(&evA, cudaEventDisableTiming);
        cudaEventCreateWithFlags(&evB, cudaEventDisableTiming);
    }

    // fork: CSR chain on s2, GEMM1 on the main stream
    cudaEventRecord(evA, 0);
    cudaStreamWaitEvent(s2, evA, 0);

    k_hist<<<(ET + 255) / 256, 256, 0, s2>>>(ei);
    k_scan1<<<NB, 1024, 0, s2>>>();
    k_scan3<<<(NN + 255) / 256, 256, 0, s2>>>();
    k_scatter<<<(ET + 1023) / 1024, 256, 0, s2>>>(ei);
    cudaEventRecord(evB, s2);

    k_gemm1<<<(NN + 127) / 128, 256>>>(x, W1, as1, ad1);

    // join
    cudaStreamWaitEvent(0, evB, 0);

    k_agg1<<<(NN * 32 + 255) / 256, 256>>>(b1);
    k_gemm2<<<(NN + 127) / 128, 256>>>(W2, bngm, bnbt, bnmu, bnvr, as2, ad2);
    k_agg2<<<(NN * 32 + 255) / 256, 256>>>(b2, out);
}

// round 7
// speedup vs baseline: 1.0732x; 1.0732x over previous
#include <cuda_runtime.h>
#include <cuda_fp16.h>
#include <math.h>

#define NN 100000
#define EE 1600000
#define ET (EE + NN)
#define FEAT 128
#define HC 64
#define NH 4
#define NC 40
#define SLOPE 0.2f
#define BNEPS 1e-5f
#define NB ((NN + 1023) / 1024)

typedef unsigned long long ull;

// ---------------- scratch ----------------
__device__ __half g_h1[NN * HC];    // layer-1 features, fp16 (gathered in agg1)
__device__ float  g_o1[NN * HC];    // layer-1 GAT output, fp32 (feeds gemm2)
__device__ __half g_h2[NN * NC];    // layer-2 features, fp16 (gathered in agg2)
__device__ float  g_as1[NN * NH];
__device__ float  g_ad1[NN * NH];
__device__ float  g_as2[NN];
__device__ float  g_ad2[NN];
__device__ int    g_rowptr[NN + 1];
__device__ int    g_cursor[NN];
__device__ int    g_cnt[NN];        // zero-initialized; every launch restores to zero
__device__ int    g_srcs[ET];
__device__ int    g_bsum[128];

// ---------------- f32x2 helpers ----------------
__device__ __forceinline__ ull fma2(ull a, ull b, ull c) {
    ull d;
    asm("fma.rn.f32x2 %0, %1, %2, %3;" : "=l"(d) : "l"(a), "l"(b), "l"(c));
    return d;
}
__device__ __forceinline__ ull splat2(float x) {
    ull r;
    asm("mov.b64 %0, {%1, %1};" : "=l"(r) : "f"(x));
    return r;
}
__device__ __forceinline__ void unpack2(ull v, float& lo, float& hi) {
    asm("mov.b64 {%0, %1}, %2;" : "=f"(lo), "=f"(hi) : "l"(v));
}

union HalfPack {
    __half2 h[2];
    uint2 u;
};
union HalfPack4 {
    __half2 h[4];
    uint4 u;
};

__device__ __forceinline__ int probe_is64(const void* ei) {
    const long long* p = (const long long*)ei;
    int is64 = 1;
#pragma unroll
    for (int j = 0; j < 8; j++) {
        long long v = p[j];
        if (v < 0 || v >= NN) { is64 = 0; break; }
    }
    return is64;
}

// ---------------- histogram (reads edge_index directly) ----------------
__global__ void k_hist(const void* ei) {
    __shared__ int sh_is64;
    if (threadIdx.x == 0) sh_is64 = probe_is64(ei);
    __syncthreads();
    int e = blockIdx.x * blockDim.x + threadIdx.x;
    if (e >= ET) return;
    int dst;
    if (e < EE) {
        dst = sh_is64 ? (int)((const long long*)ei)[EE + e] : ((const int*)ei)[EE + e];
    } else {
        dst = e - EE;
    }
    atomicAdd(&g_cnt[dst], 1);   // no return use -> RED
}

// ---------------- scan: per-block scan (restores g_cnt to zero), then fused fixup ----------------
__global__ void k_scan1() {  // blockDim = 1024
    int i = blockIdx.x * 1024 + threadIdx.x;
    int v = 0;
    if (i < NN) {
        v = g_cnt[i];
        g_cnt[i] = 0;           // restore invariant for next launch
    }
    int x = v;
#pragma unroll
    for (int o = 1; o < 32; o <<= 1) {
        int y = __shfl_up_sync(0xffffffffu, x, o);
        if ((threadIdx.x & 31) >= o) x += y;
    }
    __shared__ int ws[32];
    if ((threadIdx.x & 31) == 31) ws[threadIdx.x >> 5] = x;
    __syncthreads();
    if (threadIdx.x < 32) {
        int w = ws[threadIdx.x];
#pragma unroll
        for (int o = 1; o < 32; o <<= 1) {
            int y = __shfl_up_sync(0xffffffffu, w, o);
            if (threadIdx.x >= o) w += y;
        }
        ws[threadIdx.x] = w;
    }
    __syncthreads();
    int add = (threadIdx.x >= 32) ? ws[(threadIdx.x >> 5) - 1] : 0;
    int incl = x + add;
    if (i < NN) g_rowptr[i] = incl - v;
    if (threadIdx.x == 1023) g_bsum[blockIdx.x] = incl;
}

__global__ void k_scan3() {
    __shared__ int sb[128];
    int tid = threadIdx.x;
    if (tid < 128) sb[tid] = (tid < NB) ? g_bsum[tid] : 0;
    __syncthreads();
#pragma unroll
    for (int o = 1; o < 128; o <<= 1) {
        int t = 0;
        if (tid < 128 && tid >= o) t = sb[tid - o];
        __syncthreads();
        if (tid < 128) sb[tid] += t;
        __syncthreads();
    }
    int i = blockIdx.x * blockDim.x + tid;
    if (i < NN) {
        int blk = i >> 10;
        int r = g_rowptr[i] + (blk ? sb[blk - 1] : 0);
        g_rowptr[i] = r;
        g_cursor[i] = r;
    }
    if (i == 0) g_rowptr[NN] = ET;
}

// ---------------- scatter: 1 edge/thread (L2-traffic bound; MLP doesn't help) ----------------
__global__ void k_scatter(const void* ei) {
    __shared__ int sh_is64;
    if (threadIdx.x == 0) sh_is64 = probe_is64(ei);
    __syncthreads();
    int e = blockIdx.x * blockDim.x + threadIdx.x;
    if (e >= ET) return;
    int src, dst;
    if (e < EE) {
        if (sh_is64) {
            src = (int)((const long long*)ei)[e];
            dst = (int)((const long long*)ei)[EE + e];
        } else {
            src = ((const int*)ei)[e];
            dst = ((const int*)ei)[EE + e];
        }
    } else {
        src = e - EE;
        dst = src;
    }
    int pos = atomicAdd(&g_cursor[dst], 1);
    g_srcs[pos] = src;
}

// ---------------- GEMM1: h1 = x @ W1, fused attention scalars (f32x2), fp16 h1 store ----------------
__global__ void k_gemm1(const float* __restrict__ x, const float* __restrict__ W,
                        const float* __restrict__ attS, const float* __restrict__ attD) {
    __shared__ __align__(16) float As[32][130];
    __shared__ __align__(16) float Bs[32][64];
    int tid = threadIdx.x;
    int tx = tid & 15, ty = tid >> 4;
    int mBase = blockIdx.x * 128;

    float as_v[4], ad_v[4];
#pragma unroll
    for (int j = 0; j < 4; j++) {
        as_v[j] = attS[tx * 4 + j];
        ad_v[j] = attD[tx * 4 + j];
    }

    ull acc[4][4];
#pragma unroll
    for (int p = 0; p < 4; p++)
#pragma unroll
        for (int j = 0; j < 4; j++) acc[p][j] = 0ull;

    for (int k0 = 0; k0 < FEAT; k0 += 32) {
        for (int idx = tid; idx < 128 * 32; idx += 256) {
            int m = idx >> 5, kk = idx & 31;
            int gm = mBase + m;
            As[kk][m] = (gm < NN) ? x[gm * FEAT + k0 + kk] : 0.f;
        }
        for (int idx = tid; idx < 32 * 64; idx += 256)
            Bs[idx >> 6][idx & 63] = W[(k0 + (idx >> 6)) * HC + (idx & 63)];
        __syncthreads();
#pragma unroll
        for (int kk = 0; kk < 32; kk++) {
            float4 bv = *(const float4*)&Bs[kk][tx * 4];
            ull b0 = splat2(bv.x), b1 = splat2(bv.y), b2 = splat2(bv.z), b3 = splat2(bv.w);
#pragma unroll
            for (int p = 0; p < 4; p++) {
                ull a = *(const ull*)&As[kk][ty * 8 + 2 * p];
                acc[p][0] = fma2(a, b0, acc[p][0]);
                acc[p][1] = fma2(a, b1, acc[p][1]);
                acc[p][2] = fma2(a, b2, acc[p][2]);
                acc[p][3] = fma2(a, b3, acc[p][3]);
            }
        }
        __syncthreads();
    }

#pragma unroll
    for (int p = 0; p < 4; p++) {
        float lo[4], hi[4];
#pragma unroll
        for (int j = 0; j < 4; j++) unpack2(acc[p][j], lo[j], hi[j]);
#pragma unroll
        for (int half = 0; half < 2; half++) {
            float* f = half ? hi : lo;
            int r = 2 * p + half;
            int gm = mBase + ty * 8 + r;
            if (gm < NN) {
                HalfPack hp;
                hp.h[0] = __floats2half2_rn(f[0], f[1]);
                hp.h[1] = __floats2half2_rn(f[2], f[3]);
                *(uint2*)&g_h1[gm * HC + tx * 4] = hp.u;
                float ps = f[0] * as_v[0] + f[1] * as_v[1] + f[2] * as_v[2] + f[3] * as_v[3];
                float pd = f[0] * ad_v[0] + f[1] * ad_v[1] + f[2] * ad_v[2] + f[3] * ad_v[3];
                ps += __shfl_xor_sync(0xffffffffu, ps, 1);
                pd += __shfl_xor_sync(0xffffffffu, pd, 1);
                ps += __shfl_xor_sync(0xffffffffu, ps, 2);
                pd += __shfl_xor_sync(0xffffffffu, pd, 2);
                if ((tx & 3) == 0) {
                    g_as1[gm * NH + (tx >> 2)] = ps;
                    g_ad1[gm * NH + (tx >> 2)] = pd;
                }
            } else {
                float z = 0.f;
                z += __shfl_xor_sync(0xffffffffu, z, 1);
                z += __shfl_xor_sync(0xffffffffu, z, 1);
                z += __shfl_xor_sync(0xffffffffu, z, 2);
                z += __shfl_xor_sync(0xffffffffu, z, 2);
            }
        }
    }
}

// ---------------- layer-1 aggregation: 8 lanes/edge x uint4, 4 edges/warp-iter ----------------
__global__ void k_agg1(const float* __restrict__ bias) {
    int t = blockIdx.x * blockDim.x + threadIdx.x;
    int node = t >> 5, lane = t & 31;
    if (node >= NN) return;
    int beg = g_rowptr[node], end = g_rowptr[node + 1];

    int q = lane >> 3;           // edge slot 0..3
    int l = lane & 7;            // channel chunk: channels l*8 .. l*8+7
    int hsel = l >> 1;           // head of this chunk (8-chunk never crosses head boundary)
    float adh = g_ad1[node * NH + hsel];

    float acc[8];
#pragma unroll
    for (int j = 0; j < 8; j++) acc[j] = 0.f;
    float sex = 0.f;

    int i = beg + q;
    int s = (i < end) ? g_srcs[i] : 0;
    while (i < end) {
        int inext = i + 4;
        int snext = (inext < end) ? g_srcs[inext] : 0;
        float a = g_as1[s * NH + hsel] + adh;
        a = fmaxf(a, SLOPE * a);
        float ex = __expf(a);
        HalfPack4 hp;
        hp.u = *(const uint4*)&g_h1[s * HC + l * 8];
#pragma unroll
        for (int j = 0; j < 4; j++) {
            float2 f = __half22float2(hp.h[j]);
            acc[2 * j]     += ex * f.x;
            acc[2 * j + 1] += ex * f.y;
        }
        sex += ex;
        i = inext; s = snext;
    }
#pragma unroll
    for (int j = 0; j < 8; j++) {
        acc[j] += __shfl_xor_sync(0xffffffffu, acc[j], 8);
        acc[j] += __shfl_xor_sync(0xffffffffu, acc[j], 16);
    }
    sex += __shfl_xor_sync(0xffffffffu, sex, 8);
    sex += __shfl_xor_sync(0xffffffffu, sex, 16);

    if (q == 0) {
        float inv = 1.0f / sex;
        float4 b0 = *(const float4*)&bias[l * 8];
        float4 b1 = *(const float4*)&bias[l * 8 + 4];
        float4 o0, o1;
        o0.x = acc[0] * inv + b0.x; o0.y = acc[1] * inv + b0.y;
        o0.z = acc[2] * inv + b0.z; o0.w = acc[3] * inv + b0.w;
        o1.x = acc[4] * inv + b1.x; o1.y = acc[5] * inv + b1.y;
        o1.z = acc[6] * inv + b1.z; o1.w = acc[7] * inv + b1.w;
        *(float4*)&g_o1[node * HC + l * 8] = o0;
        *(float4*)&g_o1[node * HC + l * 8 + 4] = o1;
    }
}

// ---------------- GEMM2: h2 = relu(BN(o1)) @ W2, fused attn scalars, fp16 h2 store ----------------
__global__ void k_gemm2(const float* __restrict__ W2,
                        const float* __restrict__ gamma, const float* __restrict__ beta,
                        const float* __restrict__ mean, const float* __restrict__ var,
                        const float* __restrict__ attS, const float* __restrict__ attD) {
    __shared__ __align__(16) float As[32][130];
    __shared__ __align__(16) float Bs[32][64];
    __shared__ float sc[64], sh[64];
    int tid = threadIdx.x;
    if (tid < 64) {
        float s = gamma[tid] * rsqrtf(var[tid] + BNEPS);
        sc[tid] = s;
        sh[tid] = beta[tid] - mean[tid] * s;
    }
    __syncthreads();
    int tx = tid & 15, ty = tid >> 4;
    int mBase = blockIdx.x * 128;

    float as_v[4], ad_v[4];
#pragma unroll
    for (int j = 0; j < 4; j++) {
        int c = tx * 4 + j;
        int cc = (c < NC) ? c : NC - 1;
        as_v[j] = attS[cc];
        ad_v[j] = attD[cc];
    }

    ull acc[4][4];
#pragma unroll
    for (int p = 0; p < 4; p++)
#pragma unroll
        for (int j = 0; j < 4; j++) acc[p][j] = 0ull;

    for (int k0 = 0; k0 < HC; k0 += 32) {
        for (int idx = tid; idx < 128 * 32; idx += 256) {
            int m = idx >> 5, kk = idx & 31;
            int gm = mBase + m;
            int k = k0 + kk;
            float v = (gm < NN) ? g_o1[gm * HC + k] : 0.f;
            As[kk][m] = fmaxf(v * sc[k] + sh[k], 0.f);
        }
        for (int idx = tid; idx < 32 * 64; idx += 256) {
            int r = idx >> 6, c = idx & 63;
            Bs[r][c] = (c < NC) ? W2[(k0 + r) * NC + c] : 0.f;
        }
        __syncthreads();
#pragma unroll
        for (int kk = 0; kk < 32; kk++) {
            float4 bv = *(const float4*)&Bs[kk][tx * 4];
            ull b0 = splat2(bv.x), b1 = splat2(bv.y), b2 = splat2(bv.z), b3 = splat2(bv.w);
#pragma unroll
            for (int p = 0; p < 4; p++) {
                ull a = *(const ull*)&As[kk][ty * 8 + 2 * p];
                acc[p][0] = fma2(a, b0, acc[p][0]);
                acc[p][1] = fma2(a, b1, acc[p][1]);
                acc[p][2] = fma2(a, b2, acc[p][2]);
                acc[p][3] = fma2(a, b3, acc[p][3]);
            }
        }
        __syncthreads();
    }

#pragma unroll
    for (int p = 0; p < 4; p++) {
        float lo[4], hi[4];
#pragma unroll
        for (int j = 0; j < 4; j++) unpack2(acc[p][j], lo[j], hi[j]);
#pragma unroll
        for (int half = 0; half < 2; half++) {
            float* f = half ? hi : lo;
            int r = 2 * p + half;
            int gm = mBase + ty * 8 + r;
            float ps = 0.f, pd = 0.f;
            if (gm < NN) {
                if (tx < 10) {
                    HalfPack hp;
                    hp.h[0] = __floats2half2_rn(f[0], f[1]);
                    hp.h[1] = __floats2half2_rn(f[2], f[3]);
                    *(uint2*)&g_h2[gm * NC + tx * 4] = hp.u;
                }
                ps = f[0] * as_v[0] + f[1] * as_v[1] + f[2] * as_v[2] + f[3] * as_v[3];
                pd = f[0] * ad_v[0] + f[1] * ad_v[1] + f[2] * ad_v[2] + f[3] * ad_v[3];
            }
#pragma unroll
            for (int o = 8; o >= 1; o >>= 1) {
                ps += __shfl_xor_sync(0xffffffffu, ps, o);
                pd += __shfl_xor_sync(0xffffffffu, pd, o);
            }
            if (gm < NN && tx == 0) {
                g_as2[gm] = ps;
                g_ad2[gm] = pd;
            }
        }
    }
}

// ---------------- layer-2 aggregation: 5 lanes/edge x uint4, 6 edges/warp-iter ----------------
__global__ void k_agg2(const float* __restrict__ bias, float* __restrict__ out) {
    int t = blockIdx.x * blockDim.x + threadIdx.x;
    int node = t >> 5, lane = t & 31;
    if (node >= NN) return;
    int beg = g_rowptr[node], end = g_rowptr[node + 1];
    float ad = g_ad2[node];

    int grp = lane / 5;                // 0..5 active; lanes 30,31 idle (grp 6)
    int l = lane - grp * 5;            // 0..4; channels l*8 .. l*8+7
    float acc[8];
#pragma unroll
    for (int j = 0; j < 8; j++) acc[j] = 0.f;
    float sex = 0.f;

    if (grp < 6) {
        int i = beg + grp;
        int s = (i < end) ? g_srcs[i] : 0;
        while (i < end) {
            int inext = i + 6;
            int snext = (inext < end) ? g_srcs[inext] : 0;
            float a = g_as2[s] + ad;
            a = fmaxf(a, SLOPE * a);
            float ex = __expf(a);
            HalfPack4 hp;
            hp.u = *(const uint4*)&g_h2[s * NC + l * 8];
#pragma unroll
            for (int j = 0; j < 4; j++) {
                float2 f = __half22float2(hp.h[j]);
                acc[2 * j]     += ex * f.x;
                acc[2 * j + 1] += ex * f.y;
            }
            sex += ex;
            i = inext; s = snext;
        }
    }
    // combine 6 groups: first fold grp g -> g+3 partner (lane+15), then grps 0..2 into 0
#pragma unroll
    for (int j = 0; j < 8; j++) {
        float v = acc[j];
        v += __shfl_sync(0xffffffffu, v, lane + 15 < 32 ? lane + 15 : lane);
        float v1 = __shfl_sync(0xffffffffu, v, lane + 5 < 32 ? lane + 5 : lane);
        float v2 = __shfl_sync(0xffffffffu, v, lane + 10 < 32 ? lane + 10 : lane);
        acc[j] = v + v1 + v2;
    }
    {
        float v = sex;
        v += __shfl_sync(0xffffffffu, v, lane + 15 < 32 ? lane + 15 : lane);
        float v1 = __shfl_sync(0xffffffffu, v, lane + 5 < 32 ? lane + 5 : lane);
        float v2 = __shfl_sync(0xffffffffu, v, lane + 10 < 32 ? lane + 10 : lane);
        sex = v + v1 + v2;
    }

    if (grp == 0) {
        float inv = 1.0f / sex;
        float4 b0 = *(const float4*)&bias[l * 8];
        float4 b1 = *(const float4*)&bias[l * 8 + 4];
        float4 o0, o1;
        o0.x = acc[0] * inv + b0.x; o0.y = acc[1] * inv + b0.y;
        o0.z = acc[2] * inv + b0.z; o0.w = acc[3] * inv + b0.w;
        o1.x = acc[4] * inv + b1.x; o1.y = acc[5] * inv + b1.y;
        o1.z = acc[6] * inv + b1.z; o1.w = acc[7] * inv + b1.w;
        *(float4*)&out[node * NC + l * 8] = o0;
        *(float4*)&out[node * NC + l * 8 + 4] = o1;
    }
}

// ---------------- launch (fork-join: CSR build overlaps GEMM1) ----------------
extern "C" void kernel_launch(void* const* d_in, const int* in_sizes, int n_in,
                              void* d_out, int out_size) {
    const float* x    = (const float*)d_in[0];
    const void*  ei   = d_in[1];
    const float* W1   = (const float*)d_in[2];
    const float* as1  = (const float*)d_in[3];
    const float* ad1  = (const float*)d_in[4];
    const float* b1   = (const float*)d_in[5];
    const float* bngm = (const float*)d_in[6];
    const float* bnbt = (const float*)d_in[7];
    const float* bnmu = (const float*)d_in[8];
    const float* bnvr = (const float*)d_in[9];
    const float* W2   = (const float*)d_in[10];
    const float* as2  = (const float*)d_in[11];
    const float* ad2  = (const float*)d_in[12];
    const float* b2   = (const float*)d_in[13];
    float*       out  = (float*)d_out;

    static cudaStream_t s2 = nullptr;
    static cudaEvent_t evA = nullptr, evB = nullptr;
    if (s2 == nullptr) {
        cudaStreamCreateWithFlags(&s2, cudaStreamNonBlocking);
        cudaEventCreateWithFlags(&evA, cudaEventDisableTiming);
        cudaEventCreateWithFlags(&evB, cudaEventDisableTiming);
    }

    // fork: CSR chain on s2, GEMM1 on the main stream
    cudaEventRecord(evA, 0);
    cudaStreamWaitEvent(s2, evA, 0);

    k_hist<<<(ET + 255) / 256, 256, 0, s2>>>(ei);
    k_scan1<<<NB, 1024, 0, s2>>>();
    k_scan3<<<(NN + 255) / 256, 256, 0, s2>>>();
    k_scatter<<<(ET + 255) / 256, 256, 0, s2>>>(ei);
    cudaEventRecord(evB, s2);

    k_gemm1<<<(NN + 127) / 128, 256>>>(x, W1, as1, ad1);

    // join
    cudaStreamWaitEvent(0, evB, 0);

    k_agg1<<<(NN * 32 + 255) / 256, 256>>>(b1);
    k_gemm2<<<(NN + 127) / 128, 256>>>(W2, bngm, bnbt, bnmu, bnvr, as2, ad2);
    k_agg2<<<(NN * 32 + 255) / 256, 256>>>(b2, out);
}

// round 8
// speedup vs baseline: 1.0942x; 1.0196x over previous
#include <cuda_runtime.h>
#include <cuda_fp16.h>
#include <math.h>

#define NN 100000
#define EE 1600000
#define ET (EE + NN)
#define FEAT 128
#define HC 64
#define NH 4
#define NC 40
#define SLOPE 0.2f
#define BNEPS 1e-5f
#define NB ((NN + 1023) / 1024)
#define NSPLIT 50048              // 391 * 128, gemm2-tile aligned

typedef unsigned long long ull;

// ---------------- scratch ----------------
__device__ __half g_h1[NN * HC];       // layer-1 features, fp16
__device__ float  g_o1[NN * HC];       // layer-1 GAT output, fp32
__device__ unsigned int g_h2p[NN * 24]; // packed 96B rows: [as2 f32][12B pad][40 fp16]
__device__ float  g_as1[NN * NH];
__device__ float  g_ad1[NN * NH];
__device__ float  g_ad2[NN];
__device__ int    g_rowptr[NN + 1];
__device__ int    g_cursor[NN];
__device__ int    g_cnt[NN];           // zero-init; every launch restores to zero
__device__ int    g_srcs[ET];
__device__ int    g_bsum[128];

// ---------------- f32x2 helpers ----------------
__device__ __forceinline__ ull fma2(ull a, ull b, ull c) {
    ull d;
    asm("fma.rn.f32x2 %0, %1, %2, %3;" : "=l"(d) : "l"(a), "l"(b), "l"(c));
    return d;
}
__device__ __forceinline__ ull splat2(float x) {
    ull r;
    asm("mov.b64 %0, {%1, %1};" : "=l"(r) : "f"(x));
    return r;
}
__device__ __forceinline__ void unpack2(ull v, float& lo, float& hi) {
    asm("mov.b64 {%0, %1}, %2;" : "=f"(lo), "=f"(hi) : "l"(v));
}

union HalfPack {
    __half2 h[2];
    uint2 u;
};
union HalfPack4 {
    __half2 h[4];
    uint4 u;
};

__device__ __forceinline__ int probe_is64(const void* ei) {
    const long long* p = (const long long*)ei;
    int is64 = 1;
#pragma unroll
    for (int j = 0; j < 8; j++) {
        long long v = p[j];
        if (v < 0 || v >= NN) { is64 = 0; break; }
    }
    return is64;
}

// ---------------- histogram ----------------
__global__ void k_hist(const void* ei) {
    __shared__ int sh_is64;
    if (threadIdx.x == 0) sh_is64 = probe_is64(ei);
    __syncthreads();
    int e = blockIdx.x * blockDim.x + threadIdx.x;
    if (e >= ET) return;
    int dst;
    if (e < EE) {
        dst = sh_is64 ? (int)((const long long*)ei)[EE + e] : ((const int*)ei)[EE + e];
    } else {
        dst = e - EE;
    }
    atomicAdd(&g_cnt[dst], 1);
}

// ---------------- scan ----------------
__global__ void k_scan1() {  // blockDim = 1024
    int i = blockIdx.x * 1024 + threadIdx.x;
    int v = 0;
    if (i < NN) {
        v = g_cnt[i];
        g_cnt[i] = 0;
    }
    int x = v;
#pragma unroll
    for (int o = 1; o < 32; o <<= 1) {
        int y = __shfl_up_sync(0xffffffffu, x, o);
        if ((threadIdx.x & 31) >= o) x += y;
    }
    __shared__ int ws[32];
    if ((threadIdx.x & 31) == 31) ws[threadIdx.x >> 5] = x;
    __syncthreads();
    if (threadIdx.x < 32) {
        int w = ws[threadIdx.x];
#pragma unroll
        for (int o = 1; o < 32; o <<= 1) {
            int y = __shfl_up_sync(0xffffffffu, w, o);
            if (threadIdx.x >= o) w += y;
        }
        ws[threadIdx.x] = w;
    }
    __syncthreads();
    int add = (threadIdx.x >= 32) ? ws[(threadIdx.x >> 5) - 1] : 0;
    int incl = x + add;
    if (i < NN) g_rowptr[i] = incl - v;
    if (threadIdx.x == 1023) g_bsum[blockIdx.x] = incl;
}

__global__ void k_scan3() {
    __shared__ int sb[128];
    int tid = threadIdx.x;
    if (tid < 128) sb[tid] = (tid < NB) ? g_bsum[tid] : 0;
    __syncthreads();
#pragma unroll
    for (int o = 1; o < 128; o <<= 1) {
        int t = 0;
        if (tid < 128 && tid >= o) t = sb[tid - o];
        __syncthreads();
        if (tid < 128) sb[tid] += t;
        __syncthreads();
    }
    int i = blockIdx.x * blockDim.x + tid;
    if (i < NN) {
        int blk = i >> 10;
        int r = g_rowptr[i] + (blk ? sb[blk - 1] : 0);
        g_rowptr[i] = r;
        g_cursor[i] = r;
    }
    if (i == 0) g_rowptr[NN] = ET;
}

// ---------------- scatter ----------------
__global__ void k_scatter(const void* ei) {
    __shared__ int sh_is64;
    if (threadIdx.x == 0) sh_is64 = probe_is64(ei);
    __syncthreads();
    int e = blockIdx.x * blockDim.x + threadIdx.x;
    if (e >= ET) return;
    int src, dst;
    if (e < EE) {
        if (sh_is64) {
            src = (int)((const long long*)ei)[e];
            dst = (int)((const long long*)ei)[EE + e];
        } else {
            src = ((const int*)ei)[e];
            dst = ((const int*)ei)[EE + e];
        }
    } else {
        src = e - EE;
        dst = src;
    }
    int pos = atomicAdd(&g_cursor[dst], 1);
    g_srcs[pos] = src;
}

// ---------------- GEMM1 ----------------
__global__ void k_gemm1(const float* __restrict__ x, const float* __restrict__ W,
                        const float* __restrict__ attS, const float* __restrict__ attD) {
    __shared__ __align__(16) float As[32][130];
    __shared__ __align__(16) float Bs[32][64];
    int tid = threadIdx.x;
    int tx = tid & 15, ty = tid >> 4;
    int mBase = blockIdx.x * 128;

    float as_v[4], ad_v[4];
#pragma unroll
    for (int j = 0; j < 4; j++) {
        as_v[j] = attS[tx * 4 + j];
        ad_v[j] = attD[tx * 4 + j];
    }

    ull acc[4][4];
#pragma unroll
    for (int p = 0; p < 4; p++)
#pragma unroll
        for (int j = 0; j < 4; j++) acc[p][j] = 0ull;

    for (int k0 = 0; k0 < FEAT; k0 += 32) {
        for (int idx = tid; idx < 128 * 32; idx += 256) {
            int m = idx >> 5, kk = idx & 31;
            int gm = mBase + m;
            As[kk][m] = (gm < NN) ? x[gm * FEAT + k0 + kk] : 0.f;
        }
        for (int idx = tid; idx < 32 * 64; idx += 256)
            Bs[idx >> 6][idx & 63] = W[(k0 + (idx >> 6)) * HC + (idx & 63)];
        __syncthreads();
#pragma unroll
        for (int kk = 0; kk < 32; kk++) {
            float4 bv = *(const float4*)&Bs[kk][tx * 4];
            ull b0 = splat2(bv.x), b1 = splat2(bv.y), b2 = splat2(bv.z), b3 = splat2(bv.w);
#pragma unroll
            for (int p = 0; p < 4; p++) {
                ull a = *(const ull*)&As[kk][ty * 8 + 2 * p];
                acc[p][0] = fma2(a, b0, acc[p][0]);
                acc[p][1] = fma2(a, b1, acc[p][1]);
                acc[p][2] = fma2(a, b2, acc[p][2]);
                acc[p][3] = fma2(a, b3, acc[p][3]);
            }
        }
        __syncthreads();
    }

#pragma unroll
    for (int p = 0; p < 4; p++) {
        float lo[4], hi[4];
#pragma unroll
        for (int j = 0; j < 4; j++) unpack2(acc[p][j], lo[j], hi[j]);
#pragma unroll
        for (int half = 0; half < 2; half++) {
            float* f = half ? hi : lo;
            int r = 2 * p + half;
            int gm = mBase + ty * 8 + r;
            if (gm < NN) {
                HalfPack hp;
                hp.h[0] = __floats2half2_rn(f[0], f[1]);
                hp.h[1] = __floats2half2_rn(f[2], f[3]);
                *(uint2*)&g_h1[gm * HC + tx * 4] = hp.u;
                float ps = f[0] * as_v[0] + f[1] * as_v[1] + f[2] * as_v[2] + f[3] * as_v[3];
                float pd = f[0] * ad_v[0] + f[1] * ad_v[1] + f[2] * ad_v[2] + f[3] * ad_v[3];
                ps += __shfl_xor_sync(0xffffffffu, ps, 1);
                pd += __shfl_xor_sync(0xffffffffu, pd, 1);
                ps += __shfl_xor_sync(0xffffffffu, ps, 2);
                pd += __shfl_xor_sync(0xffffffffu, pd, 2);
                if ((tx & 3) == 0) {
                    g_as1[gm * NH + (tx >> 2)] = ps;
                    g_ad1[gm * NH + (tx >> 2)] = pd;
                }
            } else {
                float z = 0.f;
                z += __shfl_xor_sync(0xffffffffu, z, 1);
                z += __shfl_xor_sync(0xffffffffu, z, 1);
                z += __shfl_xor_sync(0xffffffffu, z, 2);
                z += __shfl_xor_sync(0xffffffffu, z, 2);
            }
        }
    }
}

// ---------------- layer-1 aggregation (node range [nodeBase, nodeEnd)) ----------------
__global__ void k_agg1(const float* __restrict__ bias, int nodeBase, int nodeEnd) {
    int t = blockIdx.x * blockDim.x + threadIdx.x;
    int node = nodeBase + (t >> 5);
    int lane = t & 31;
    if (node >= nodeEnd) return;
    int beg = g_rowptr[node], end = g_rowptr[node + 1];

    int q = lane >> 3;           // edge slot 0..3
    int l = lane & 7;            // channel chunk: channels l*8 .. l*8+7
    int hsel = l >> 1;           // head of this chunk
    float adh = g_ad1[node * NH + hsel];

    float acc[8];
#pragma unroll
    for (int j = 0; j < 8; j++) acc[j] = 0.f;
    float sex = 0.f;

    int i = beg + q;
    int s = (i < end) ? g_srcs[i] : 0;
    while (i < end) {
        int inext = i + 4;
        int snext = (inext < end) ? g_srcs[inext] : 0;
        float a = g_as1[s * NH + hsel] + adh;
        a = fmaxf(a, SLOPE * a);
        float ex = __expf(a);
        HalfPack4 hp;
        hp.u = *(const uint4*)&g_h1[s * HC + l * 8];
#pragma unroll
        for (int j = 0; j < 4; j++) {
            float2 f = __half22float2(hp.h[j]);
            acc[2 * j]     += ex * f.x;
            acc[2 * j + 1] += ex * f.y;
        }
        sex += ex;
        i = inext; s = snext;
    }
#pragma unroll
    for (int j = 0; j < 8; j++) {
        acc[j] += __shfl_xor_sync(0xffffffffu, acc[j], 8);
        acc[j] += __shfl_xor_sync(0xffffffffu, acc[j], 16);
    }
    sex += __shfl_xor_sync(0xffffffffu, sex, 8);
    sex += __shfl_xor_sync(0xffffffffu, sex, 16);

    if (q == 0) {
        float inv = 1.0f / sex;
        float4 b0 = *(const float4*)&bias[l * 8];
        float4 b1 = *(const float4*)&bias[l * 8 + 4];
        float4 o0, o1;
        o0.x = acc[0] * inv + b0.x; o0.y = acc[1] * inv + b0.y;
        o0.z = acc[2] * inv + b0.z; o0.w = acc[3] * inv + b0.w;
        o1.x = acc[4] * inv + b1.x; o1.y = acc[5] * inv + b1.y;
        o1.z = acc[6] * inv + b1.z; o1.w = acc[7] * inv + b1.w;
        *(float4*)&g_o1[node * HC + l * 8] = o0;
        *(float4*)&g_o1[node * HC + l * 8 + 4] = o1;
    }
}

// ---------------- GEMM2 (block range offset; packed h2 row store) ----------------
__global__ void k_gemm2(const float* __restrict__ W2,
                        const float* __restrict__ gamma, const float* __restrict__ beta,
                        const float* __restrict__ mean, const float* __restrict__ var,
                        const float* __restrict__ attS, const float* __restrict__ attD,
                        int blockOff) {
    __shared__ __align__(16) float As[32][130];
    __shared__ __align__(16) float Bs[32][64];
    __shared__ float sc[64], sh[64];
    int tid = threadIdx.x;
    if (tid < 64) {
        float s = gamma[tid] * rsqrtf(var[tid] + BNEPS);
        sc[tid] = s;
        sh[tid] = beta[tid] - mean[tid] * s;
    }
    __syncthreads();
    int tx = tid & 15, ty = tid >> 4;
    int mBase = (blockIdx.x + blockOff) * 128;

    float as_v[4], ad_v[4];
#pragma unroll
    for (int j = 0; j < 4; j++) {
        int c = tx * 4 + j;
        int cc = (c < NC) ? c : NC - 1;
        as_v[j] = attS[cc];
        ad_v[j] = attD[cc];
    }

    ull acc[4][4];
#pragma unroll
    for (int p = 0; p < 4; p++)
#pragma unroll
        for (int j = 0; j < 4; j++) acc[p][j] = 0ull;

    for (int k0 = 0; k0 < HC; k0 += 32) {
        for (int idx = tid; idx < 128 * 32; idx += 256) {
            int m = idx >> 5, kk = idx & 31;
            int gm = mBase + m;
            int k = k0 + kk;
            float v = (gm < NN) ? g_o1[gm * HC + k] : 0.f;
            As[kk][m] = fmaxf(v * sc[k] + sh[k], 0.f);
        }
        for (int idx = tid; idx < 32 * 64; idx += 256) {
            int r = idx >> 6, c = idx & 63;
            Bs[r][c] = (c < NC) ? W2[(k0 + r) * NC + c] : 0.f;
        }
        __syncthreads();
#pragma unroll
        for (int kk = 0; kk < 32; kk++) {
            float4 bv = *(const float4*)&Bs[kk][tx * 4];
            ull b0 = splat2(bv.x), b1 = splat2(bv.y), b2 = splat2(bv.z), b3 = splat2(bv.w);
#pragma unroll
            for (int p = 0; p < 4; p++) {
                ull a = *(const ull*)&As[kk][ty * 8 + 2 * p];
                acc[p][0] = fma2(a, b0, acc[p][0]);
                acc[p][1] = fma2(a, b1, acc[p][1]);
                acc[p][2] = fma2(a, b2, acc[p][2]);
                acc[p][3] = fma2(a, b3, acc[p][3]);
            }
        }
        __syncthreads();
    }

#pragma unroll
    for (int p = 0; p < 4; p++) {
        float lo[4], hi[4];
#pragma unroll
        for (int j = 0; j < 4; j++) unpack2(acc[p][j], lo[j], hi[j]);
#pragma unroll
        for (int half = 0; half < 2; half++) {
            float* f = half ? hi : lo;
            int r = 2 * p + half;
            int gm = mBase + ty * 8 + r;
            float ps = 0.f, pd = 0.f;
            if (gm < NN) {
                if (tx < 10) {
                    HalfPack hp;
                    hp.h[0] = __floats2half2_rn(f[0], f[1]);
                    hp.h[1] = __floats2half2_rn(f[2], f[3]);
                    // packed row: channels start at byte 16 (uint index 4)
                    *(uint2*)&g_h2p[gm * 24 + 4 + tx * 2] = hp.u;
                }
                ps = f[0] * as_v[0] + f[1] * as_v[1] + f[2] * as_v[2] + f[3] * as_v[3];
                pd = f[0] * ad_v[0] + f[1] * ad_v[1] + f[2] * ad_v[2] + f[3] * ad_v[3];
            }
#pragma unroll
            for (int o = 8; o >= 1; o >>= 1) {
                ps += __shfl_xor_sync(0xffffffffu, ps, o);
                pd += __shfl_xor_sync(0xffffffffu, pd, o);
            }
            if (gm < NN && tx == 0) {
                ((float*)g_h2p)[gm * 24] = ps;   // as2 packed at row head
                g_ad2[gm] = pd;
            }
        }
    }
}

// ---------------- layer-2 aggregation: packed rows, 3 sectors/edge ----------------
__global__ void k_agg2(const float* __restrict__ bias, float* __restrict__ out) {
    int t = blockIdx.x * blockDim.x + threadIdx.x;
    int node = t >> 5, lane = t & 31;
    if (node >= NN) return;
    int beg = g_rowptr[node], end = g_rowptr[node + 1];
    float ad = g_ad2[node];

    int grp = lane / 5;                // 0..5 active; lanes 30,31 idle (grp 6)
    int l = lane - grp * 5;            // 0..4; channels l*8 .. l*8+7
    float acc[8];
#pragma unroll
    for (int j = 0; j < 8; j++) acc[j] = 0.f;
    float sex = 0.f;

    if (grp < 6) {
        int i = beg + grp;
        int s = (i < end) ? g_srcs[i] : 0;
        while (i < end) {
            int inext = i + 6;
            int snext = (inext < end) ? g_srcs[inext] : 0;
            const unsigned int* row = &g_h2p[s * 24];
            float a = __int_as_float(row[0]) + ad;  // as2 at row head
            a = fmaxf(a, SLOPE * a);
            float ex = __expf(a);
            HalfPack4 hp;
            hp.u = *(const uint4*)(row + 4 + l * 4);
#pragma unroll
            for (int j = 0; j < 4; j++) {
                float2 f = __half22float2(hp.h[j]);
                acc[2 * j]     += ex * f.x;
                acc[2 * j + 1] += ex * f.y;
            }
            sex += ex;
            i = inext; s = snext;
        }
    }
#pragma unroll
    for (int j = 0; j < 8; j++) {
        float v = acc[j];
        v += __shfl_sync(0xffffffffu, v, lane + 15 < 32 ? lane + 15 : lane);
        float v1 = __shfl_sync(0xffffffffu, v, lane + 5 < 32 ? lane + 5 : lane);
        float v2 = __shfl_sync(0xffffffffu, v, lane + 10 < 32 ? lane + 10 : lane);
        acc[j] = v + v1 + v2;
    }
    {
        float v = sex;
        v += __shfl_sync(0xffffffffu, v, lane + 15 < 32 ? lane + 15 : lane);
        float v1 = __shfl_sync(0xffffffffu, v, lane + 5 < 32 ? lane + 5 : lane);
        float v2 = __shfl_sync(0xffffffffu, v, lane + 10 < 32 ? lane + 10 : lane);
        sex = v + v1 + v2;
    }

    if (grp == 0) {
        float inv = 1.0f / sex;
        float4 b0 = *(const float4*)&bias[l * 8];
        float4 b1 = *(const float4*)&bias[l * 8 + 4];
        float4 o0, o1;
        o0.x = acc[0] * inv + b0.x; o0.y = acc[1] * inv + b0.y;
        o0.z = acc[2] * inv + b0.z; o0.w = acc[3] * inv + b0.w;
        o1.x = acc[4] * inv + b1.x; o1.y = acc[5] * inv + b1.y;
        o1.z = acc[6] * inv + b1.z; o1.w = acc[7] * inv + b1.w;
        *(float4*)&out[node * NC + l * 8] = o0;
        *(float4*)&out[node * NC + l * 8 + 4] = o1;
    }
}

// ---------------- launch: CSR ∥ gemm1, then agg1/gemm2 pipelined by halves ----------------
extern "C" void kernel_launch(void* const* d_in, const int* in_sizes, int n_in,
                              void* d_out, int out_size) {
    const float* x    = (const float*)d_in[0];
    const void*  ei   = d_in[1];
    const float* W1   = (const float*)d_in[2];
    const float* as1  = (const float*)d_in[3];
    const float* ad1  = (const float*)d_in[4];
    const float* b1   = (const float*)d_in[5];
    const float* bngm = (const float*)d_in[6];
    const float* bnbt = (const float*)d_in[7];
    const float* bnmu = (const float*)d_in[8];
    const float* bnvr = (const float*)d_in[9];
    const float* W2   = (const float*)d_in[10];
    const float* as2  = (const float*)d_in[11];
    const float* ad2  = (const float*)d_in[12];
    const float* b2   = (const float*)d_in[13];
    float*       out  = (float*)d_out;

    static cudaStream_t s2 = nullptr;
    static cudaEvent_t evA = nullptr, evB = nullptr, evG = nullptr, evD = nullptr;
    if (s2 == nullptr) {
        cudaStreamCreateWithFlags(&s2, cudaStreamNonBlocking);
        cudaEventCreateWithFlags(&evA, cudaEventDisableTiming);
        cudaEventCreateWithFlags(&evB, cudaEventDisableTiming);
        cudaEventCreateWithFlags(&evG, cudaEventDisableTiming);
        cudaEventCreateWithFlags(&evD, cudaEventDisableTiming);
    }

    const int nA = NSPLIT;                 // nodes [0, NSPLIT)
    const int gemm2BlocksA = NSPLIT / 128; // 391
    const int gemm2BlocksB = (NN - NSPLIT + 127) / 128 + 1; // covers rest

    // fork: CSR chain on s2, GEMM1 on main stream
    cudaEventRecord(evA, 0);
    cudaStreamWaitEvent(s2, evA, 0);

    k_hist<<<(ET + 255) / 256, 256, 0, s2>>>(ei);
    k_scan1<<<NB, 1024, 0, s2>>>();
    k_scan3<<<(NN + 255) / 256, 256, 0, s2>>>();
    k_scatter<<<(ET + 255) / 256, 256, 0, s2>>>(ei);
    cudaEventRecord(evB, s2);

    k_gemm1<<<(NN + 127) / 128, 256>>>(x, W1, as1, ad1);
    cudaEventRecord(evG, 0);

    // join CSR into main stream; gemm1 into s2
    cudaStreamWaitEvent(0, evB, 0);
    cudaStreamWaitEvent(s2, evG, 0);

    // pipeline: half A on main, half B on s2
    k_agg1<<<(nA * 32 + 255) / 256, 256>>>(b1, 0, nA);
    k_gemm2<<<gemm2BlocksA, 256>>>(W2, bngm, bnbt, bnmu, bnvr, as2, ad2, 0);

    k_agg1<<<((NN - nA) * 32 + 255) / 256, 256, 0, s2>>>(b1, nA, NN);
    k_gemm2<<<gemm2BlocksB, 256, 0, s2>>>(W2, bngm, bnbt, bnmu, bnvr, as2, ad2, gemm2BlocksA);
    cudaEventRecord(evD, s2);

    cudaStreamWaitEvent(0, evD, 0);
    k_agg2<<<(NN * 32 + 255) / 256, 256>>>(b2, out);
}